// round 1
// baseline (speedup 1.0000x reference)
#include <cuda_runtime.h>
#include <math.h>

// Problem constants (fixed shapes)
#define Bg   8
#define Nn   20000
#define Eg   320000
#define Cc   128
#define Dd   64
#define HOPSN 4
#define HIDN 512
#define OUTN 256
#define CAP  96
#define NROW (Bg*Nn)   // 160000

typedef unsigned long long ull;

// ---------------- device scratch (static, allowed) ----------------
__device__ int   g_cnt[NROW];
__device__ int   g_adj[(size_t)NROW*CAP];          // 61.4 MB
__device__ int   g_idx[Nn];
__device__ float g_init[Nn*Dd];                    // 5.1 MB
__device__ float g_omega[(size_t)NROW*HOPSN*Dd];   // 163.8 MB  layout [row][hop][64]
__device__ float g_w1p[HOPSN*Dd*HIDN];             // permuted W1

// ---------------- f32x2 packed helpers ----------------
__device__ __forceinline__ ull ffma2(ull a, ull b, ull c){
    ull d; asm("fma.rn.f32x2 %0,%1,%2,%3;" : "=l"(d) : "l"(a), "l"(b), "l"(c)); return d;
}
__device__ __forceinline__ ull add2(ull a, ull b){
    ull d; asm("add.rn.f32x2 %0,%1,%2;" : "=l"(d) : "l"(a), "l"(b)); return d;
}
__device__ __forceinline__ ull dup2(float x){
    ull r; asm("mov.b64 %0,{%1,%1};" : "=l"(r) : "f"(x)); return r;
}
__device__ __forceinline__ float2 unpk(ull v){
    float2 f; asm("mov.b64 {%0,%1},%2;" : "=f"(f.x), "=f"(f.y) : "l"(v)); return f;
}

// ---------------- small kernels ----------------
__global__ void k_zero_cnt(){
    int i = blockIdx.x*blockDim.x + threadIdx.x;
    if (i < NROW) g_cnt[i] = 0;
}

__global__ void k_build(const int* __restrict__ edges){
    int i = blockIdx.x*blockDim.x + threadIdx.x;
    if (i >= Bg*Eg) return;
    int b = i / Eg, e = i % Eg;
    const int* eb = edges + (size_t)b*2*Eg;
    int r = eb[e];        // destination (segment id)
    int c = eb[Eg + e];   // source
    int row = b*Nn + r;
    int slot = atomicAdd(&g_cnt[row], 1);
    if (slot < CAP) g_adj[(size_t)row*CAP + slot] = c;
}

__global__ void k_argmax(const float* __restrict__ poh){
    int n = blockIdx.x*blockDim.x + threadIdx.x;
    if (n >= Nn) return;
    float best = poh[n]; int bi = 0;
    #pragma unroll 4
    for (int c = 1; c < Cc; c++){
        float v = poh[(size_t)c*Nn + n];
        if (v > best){ best = v; bi = c; }
    }
    g_idx[n] = bi;
}

__global__ void k_gather(const float* __restrict__ emb){
    int i = blockIdx.x*blockDim.x + threadIdx.x;
    if (i >= Nn*16) return;
    int n = i >> 4, l = i & 15;
    float4 v = *(const float4*)(emb + (size_t)g_idx[n]*Dd + l*4);
    *(float4*)(g_init + (size_t)n*Dd + l*4) = v;
}

// W1perm[(h*64+d)*512+j] = W1[(d*4+h)*512+j]  (matches stack(...,-1).reshape)
__global__ void k_permw1(const float* __restrict__ W1){
    int i = blockIdx.x*blockDim.x + threadIdx.x;
    if (i >= HOPSN*Dd*HIDN) return;
    int k = i / HIDN, j = i % HIDN;
    int h = k / Dd, d = k % Dd;
    g_w1p[i] = W1[(size_t)(d*HOPSN + h)*HIDN + j];
}

// One 16-lane group per output row; pure gather, no atomics, no clears.
__global__ void k_hop(int hop){
    int gid = blockIdx.x*blockDim.x + threadIdx.x;
    int row = gid >> 4, lane = gid & 15;
    if (row >= NROW) return;
    int b = row / Nn;
    const float* src; int rs;
    if (hop == 1){ src = g_init + lane*4; rs = Dd; }
    else         { src = g_omega + (size_t)b*Nn*(HOPSN*Dd) + (hop-2)*Dd + lane*4; rs = HOPSN*Dd; }
    int cnt = g_cnt[row]; if (cnt > CAP) cnt = CAP;
    const int* adj = g_adj + (size_t)row*CAP;
    float4 s0 = make_float4(0.f,0.f,0.f,0.f);
    float4 s1 = make_float4(0.f,0.f,0.f,0.f);
    int j = 0;
    for (; j + 2 <= cnt; j += 2){
        int c0 = adj[j], c1 = adj[j+1];
        float4 v0 = *(const float4*)(src + (size_t)c0*rs);
        float4 v1 = *(const float4*)(src + (size_t)c1*rs);
        s0.x += v0.x; s0.y += v0.y; s0.z += v0.z; s0.w += v0.w;
        s1.x += v1.x; s1.y += v1.y; s1.z += v1.z; s1.w += v1.w;
    }
    if (j < cnt){
        float4 v = *(const float4*)(src + (size_t)adj[j]*rs);
        s0.x += v.x; s0.y += v.y; s0.z += v.z; s0.w += v.w;
    }
    float4 r = make_float4(s0.x+s1.x, s0.y+s1.y, s0.z+s1.z, s0.w+s1.w);
    *(float4*)(g_omega + (size_t)row*(HOPSN*Dd) + (hop-1)*Dd + lane*4) = r;
}

// ---------------- fused MLP kernel ----------------
// Per 64-row tile: X = A@W1p + b1 -> LN -> GELU -> OUT = X@W2 + b2
// As: [256][64] (A transposed, k-major).  Bs: 2x[16][128] double buffer (also LN scratch).
// Xs: [512][66] (X transposed, row dim padded to 66 for bank spread + 8B pair alignment).
#define SMEM_FLOATS (16384 + 4096 + 512*66)
#define SMEM_BYTES  (SMEM_FLOATS*4)

// One col-chunk GEMM: acc[4][4] over rows (r0 + 2*i2 {lo,hi}) x cols (c0 + j*32 + ct)
__device__ __forceinline__ void gemm_chunk(
    const float* __restrict__ AT, int lda,
    const float* __restrict__ W, int ldW, int NK, int c0,
    float* Bs, int tid, int r0, int ct, ull acc[4][4])
{
    int kr0 = tid >> 5;          // 0..7
    int cq0 = (tid & 31) * 4;    // 0..124
    // prologue: fill buffer 0 (k-chunk 0)
    {
        const float* Wp = W + c0;
        *(float4*)(Bs + kr0*128 + cq0)      = *(const float4*)(Wp + (size_t)kr0*ldW + cq0);
        *(float4*)(Bs + (kr0+8)*128 + cq0)  = *(const float4*)(Wp + (size_t)(kr0+8)*ldW + cq0);
    }
    __syncthreads();
    for (int kc = 0; kc < NK; kc++){
        int cur = kc & 1;
        float4 st0, st1;
        bool pre = (kc + 1 < NK);
        if (pre){
            const float* Wp = W + (size_t)((kc+1)*16)*ldW + c0;
            st0 = *(const float4*)(Wp + (size_t)kr0*ldW + cq0);
            st1 = *(const float4*)(Wp + (size_t)(kr0+8)*ldW + cq0);
        }
        const float* Ak = AT + (size_t)(kc*16)*lda + r0;
        const float* Bb = Bs + cur*2048 + ct;
        #pragma unroll
        for (int kk = 0; kk < 16; kk++){
            const ull* ap = (const ull*)(Ak + kk*lda);
            ull a0 = ap[0], a1 = ap[1], a2 = ap[2], a3 = ap[3];
            const float* bp = Bb + kk*128;
            ull q0 = dup2(bp[0]), q1 = dup2(bp[32]), q2 = dup2(bp[64]), q3 = dup2(bp[96]);
            acc[0][0] = ffma2(a0, q0, acc[0][0]);
            acc[1][0] = ffma2(a1, q0, acc[1][0]);
            acc[2][0] = ffma2(a2, q0, acc[2][0]);
            acc[3][0] = ffma2(a3, q0, acc[3][0]);
            acc[0][1] = ffma2(a0, q1, acc[0][1]);
            acc[1][1] = ffma2(a1, q1, acc[1][1]);
            acc[2][1] = ffma2(a2, q1, acc[2][1]);
            acc[3][1] = ffma2(a3, q1, acc[3][1]);
            acc[0][2] = ffma2(a0, q2, acc[0][2]);
            acc[1][2] = ffma2(a1, q2, acc[1][2]);
            acc[2][2] = ffma2(a2, q2, acc[2][2]);
            acc[3][2] = ffma2(a3, q2, acc[3][2]);
            acc[0][3] = ffma2(a0, q3, acc[0][3]);
            acc[1][3] = ffma2(a1, q3, acc[1][3]);
            acc[2][3] = ffma2(a2, q3, acc[2][3]);
            acc[3][3] = ffma2(a3, q3, acc[3][3]);
        }
        if (pre){
            float* dst = Bs + (cur^1)*2048;
            *(float4*)(dst + kr0*128 + cq0)     = st0;
            *(float4*)(dst + (kr0+8)*128 + cq0) = st1;
        }
        __syncthreads();
    }
}

__global__ void __launch_bounds__(256,1) k_mlp(
    const float* __restrict__ b1v, const float* __restrict__ gamma,
    const float* __restrict__ beta, const float* __restrict__ W2,
    const float* __restrict__ b2v, float* __restrict__ out)
{
    extern __shared__ float sm[];
    float* As = sm;                     // 16384 floats
    float* Bs = sm + 16384;             // 4096 floats (also LN scratch)
    float* Xs = sm + 16384 + 4096;      // 512*66 floats

    int tid  = threadIdx.x;
    int warp = tid >> 5, ct = tid & 31;
    int r0   = warp * 8;
    int rowBase = blockIdx.x * 64;

    // ---- load A tile transposed into As[k][row] ----
    {
        int row = tid & 63, seg = tid >> 6;
        const float* src = g_omega + (size_t)(rowBase + row)*256 + seg*64;
        #pragma unroll
        for (int i = 0; i < 16; i++){
            float4 v = *(const float4*)(src + i*4);
            int k = seg*64 + i*4;
            As[(k+0)*64 + row] = v.x;
            As[(k+1)*64 + row] = v.y;
            As[(k+2)*64 + row] = v.z;
            As[(k+3)*64 + row] = v.w;
        }
    }
    __syncthreads();

    // ---- GEMM1: 4 col-chunks of 128, K=256 ----
    for (int cc = 0; cc < 4; cc++){
        int c0 = cc * 128;
        ull acc[4][4];
        #pragma unroll
        for (int i = 0; i < 4; i++)
            #pragma unroll
            for (int j = 0; j < 4; j++) acc[i][j] = 0ULL;

        gemm_chunk(As, 64, g_w1p, HIDN, 16, c0, Bs, tid, r0, ct, acc);

        // epilogue: + b1, store transposed to Xs[col][rowpair]
        #pragma unroll
        for (int j = 0; j < 4; j++){
            int col = c0 + j*32 + ct;
            ull bb = dup2(b1v[col]);
            #pragma unroll
            for (int i2 = 0; i2 < 4; i2++){
                *(ull*)(Xs + col*66 + r0 + i2*2) = add2(acc[i2][j], bb);
            }
        }
        __syncthreads();
    }

    // ---- LayerNorm + GELU (in place on Xs) ----
    {
        int r = tid & 63, q = tid >> 6;
        float s = 0.f, s2 = 0.f;
        for (int c = q*128; c < q*128 + 128; c++){
            float v = Xs[c*66 + r];
            s += v; s2 += v*v;
        }
        Bs[tid] = s; Bs[256 + tid] = s2;
        __syncthreads();
        if (q == 0){
            float S  = Bs[r] + Bs[64+r] + Bs[128+r] + Bs[192+r];
            float S2 = Bs[256+r] + Bs[320+r] + Bs[384+r] + Bs[448+r];
            float mu  = S * (1.f/512.f);
            float var = S2 * (1.f/512.f) - mu*mu;
            Bs[512 + r] = mu;
            Bs[576 + r] = rsqrtf(var + 1e-5f);
        }
        __syncthreads();
        float mu = Bs[512 + r], rs = Bs[576 + r];
        for (int c = q*128; c < q*128 + 128; c++){
            float v = Xs[c*66 + r];
            v = (v - mu) * rs * gamma[c] + beta[c];
            v = 0.5f * v * (1.f + erff(v * 0.70710678118654752f));
            Xs[c*66 + r] = v;
        }
        __syncthreads();
    }

    // ---- GEMM2: 2 col-chunks of 128, K=512 ----
    for (int cc = 0; cc < 2; cc++){
        int c0 = cc * 128;
        ull acc[4][4];
        #pragma unroll
        for (int i = 0; i < 4; i++)
            #pragma unroll
            for (int j = 0; j < 4; j++) acc[i][j] = 0ULL;

        gemm_chunk(Xs, 66, W2, OUTN, 32, c0, Bs, tid, r0, ct, acc);

        // epilogue: + b2, write to global (coalesced STG.32)
        #pragma unroll
        for (int j = 0; j < 4; j++){
            int col = c0 + j*32 + ct;
            float bias = b2v[col];
            #pragma unroll
            for (int i2 = 0; i2 < 4; i2++){
                float2 v = unpk(acc[i2][j]);
                size_t rg = (size_t)(rowBase + r0 + i2*2);
                out[rg*OUTN + col]       = v.x + bias;
                out[(rg+1)*OUTN + col]   = v.y + bias;
            }
        }
        __syncthreads();
    }
}

// ---------------- launch ----------------
extern "C" void kernel_launch(void* const* d_in, const int* in_sizes, int n_in,
                              void* d_out, int out_size)
{
    const int* edges = (const int*)d_in[0];
    // num_nodes may or may not be materialized as a scalar input at slot 1
    int p = (in_sizes[1] <= 2) ? 2 : 1;
    const float* poh   = (const float*)d_in[p+0];
    const float* emb   = (const float*)d_in[p+1];
    const float* W1    = (const float*)d_in[p+2];
    const float* b1    = (const float*)d_in[p+3];
    const float* gamma = (const float*)d_in[p+4];
    const float* beta  = (const float*)d_in[p+5];
    const float* W2    = (const float*)d_in[p+6];
    const float* b2    = (const float*)d_in[p+7];
    float* out = (float*)d_out;

    cudaFuncSetAttribute(k_mlp, cudaFuncAttributeMaxDynamicSharedMemorySize, SMEM_BYTES);

    k_zero_cnt<<<(NROW + 255)/256, 256>>>();
    k_build  <<<(Bg*Eg + 255)/256, 256>>>(edges);
    k_argmax <<<(Nn + 255)/256, 256>>>(poh);
    k_gather <<<(Nn*16 + 255)/256, 256>>>(emb);
    k_permw1 <<<(HOPSN*Dd*HIDN + 255)/256, 256>>>(W1);
    for (int h = 1; h <= HOPSN; h++)
        k_hop<<<(NROW*16 + 255)/256, 256>>>(h);
    k_mlp<<<NROW/64, 256, SMEM_BYTES>>>(b1, gamma, beta, W2, b2, out);
}

// round 2
// speedup vs baseline: 1.0004x; 1.0004x over previous
#include <cuda_runtime.h>
#include <math.h>

// Problem constants (fixed shapes)
#define Bg   8
#define Nn   20000
#define Eg   320000
#define Cc   128
#define Dd   64
#define HOPSN 4
#define HIDN 512
#define OUTN 256
#define CAP  96
#define NROW (Bg*Nn)   // 160000

typedef unsigned long long ull;

// ---------------- device scratch (static, allowed) ----------------
__device__ int   g_cnt[NROW];
__device__ int   g_adj[(size_t)NROW*CAP];          // 61.4 MB
__device__ int   g_idx[Nn];
__device__ float g_init[Nn*Dd];                    // 5.1 MB
__device__ float g_omega[(size_t)NROW*HOPSN*Dd];   // 163.8 MB  layout [row][hop][64]
__device__ float g_w1p[HOPSN*Dd*HIDN];             // permuted W1

// ---------------- f32x2 packed helpers ----------------
__device__ __forceinline__ ull ffma2(ull a, ull b, ull c){
    ull d; asm("fma.rn.f32x2 %0,%1,%2,%3;" : "=l"(d) : "l"(a), "l"(b), "l"(c)); return d;
}
__device__ __forceinline__ ull add2(ull a, ull b){
    ull d; asm("add.rn.f32x2 %0,%1,%2;" : "=l"(d) : "l"(a), "l"(b)); return d;
}
__device__ __forceinline__ ull dup2(float x){
    ull r; asm("mov.b64 %0,{%1,%1};" : "=l"(r) : "f"(x)); return r;
}
__device__ __forceinline__ float2 unpk(ull v){
    float2 f; asm("mov.b64 {%0,%1},%2;" : "=f"(f.x), "=f"(f.y) : "l"(v)); return f;
}

// ---------------- small kernels ----------------
__global__ void k_zero_cnt(){
    int i = blockIdx.x*blockDim.x + threadIdx.x;
    if (i < NROW) g_cnt[i] = 0;
}

__global__ void k_build(const int* __restrict__ edges){
    int i = blockIdx.x*blockDim.x + threadIdx.x;
    if (i >= Bg*Eg) return;
    int b = i / Eg, e = i % Eg;
    const int* eb = edges + (size_t)b*2*Eg;
    int r = eb[e];        // destination (segment id)
    int c = eb[Eg + e];   // source
    int row = b*Nn + r;
    int slot = atomicAdd(&g_cnt[row], 1);
    if (slot < CAP) g_adj[(size_t)row*CAP + slot] = c;
}

__global__ void k_argmax(const float* __restrict__ poh){
    int n = blockIdx.x*blockDim.x + threadIdx.x;
    if (n >= Nn) return;
    float best = poh[n]; int bi = 0;
    #pragma unroll 4
    for (int c = 1; c < Cc; c++){
        float v = poh[(size_t)c*Nn + n];
        if (v > best){ best = v; bi = c; }
    }
    g_idx[n] = bi;
}

__global__ void k_gather(const float* __restrict__ emb){
    int i = blockIdx.x*blockDim.x + threadIdx.x;
    if (i >= Nn*16) return;
    int n = i >> 4, l = i & 15;
    float4 v = *(const float4*)(emb + (size_t)g_idx[n]*Dd + l*4);
    *(float4*)(g_init + (size_t)n*Dd + l*4) = v;
}

// W1perm[(h*64+d)*512+j] = W1[(d*4+h)*512+j]  (matches stack(...,-1).reshape)
__global__ void k_permw1(const float* __restrict__ W1){
    int i = blockIdx.x*blockDim.x + threadIdx.x;
    if (i >= HOPSN*Dd*HIDN) return;
    int k = i / HIDN, j = i % HIDN;
    int h = k / Dd, d = k % Dd;
    g_w1p[i] = W1[(size_t)(d*HOPSN + h)*HIDN + j];
}

// One 16-lane group per output row; pure gather, no atomics, no clears.
__global__ void k_hop(int hop){
    int gid = blockIdx.x*blockDim.x + threadIdx.x;
    int row = gid >> 4, lane = gid & 15;
    if (row >= NROW) return;
    int b = row / Nn;
    const float* src; int rs;
    if (hop == 1){ src = g_init + lane*4; rs = Dd; }
    else         { src = g_omega + (size_t)b*Nn*(HOPSN*Dd) + (hop-2)*Dd + lane*4; rs = HOPSN*Dd; }
    int cnt = g_cnt[row]; if (cnt > CAP) cnt = CAP;
    const int* adj = g_adj + (size_t)row*CAP;
    float4 s0 = make_float4(0.f,0.f,0.f,0.f);
    float4 s1 = make_float4(0.f,0.f,0.f,0.f);
    int j = 0;
    for (; j + 2 <= cnt; j += 2){
        int c0 = adj[j], c1 = adj[j+1];
        float4 v0 = *(const float4*)(src + (size_t)c0*rs);
        float4 v1 = *(const float4*)(src + (size_t)c1*rs);
        s0.x += v0.x; s0.y += v0.y; s0.z += v0.z; s0.w += v0.w;
        s1.x += v1.x; s1.y += v1.y; s1.z += v1.z; s1.w += v1.w;
    }
    if (j < cnt){
        float4 v = *(const float4*)(src + (size_t)adj[j]*rs);
        s0.x += v.x; s0.y += v.y; s0.z += v.z; s0.w += v.w;
    }
    float4 r = make_float4(s0.x+s1.x, s0.y+s1.y, s0.z+s1.z, s0.w+s1.w);
    *(float4*)(g_omega + (size_t)row*(HOPSN*Dd) + (hop-1)*Dd + lane*4) = r;
}

// ---------------- fused MLP kernel ----------------
// Per 64-row tile: X = A@W1p + b1 -> LN -> GELU -> OUT = X@W2 + b2
// As: [256][64] (A transposed, k-major).  Bs: 2x[16][128] double buffer (also LN scratch).
// Xs: [512][66] (X transposed, row dim padded to 66 for bank spread + 8B pair alignment).
#define SMEM_FLOATS (16384 + 4096 + 512*66)
#define SMEM_BYTES  (SMEM_FLOATS*4)

// One col-chunk GEMM: acc[4][4] over rows (r0 + 2*i2 {lo,hi}) x cols (c0 + j*32 + ct)
__device__ __forceinline__ void gemm_chunk(
    const float* __restrict__ AT, int lda,
    const float* __restrict__ W, int ldW, int NK, int c0,
    float* Bs, int tid, int r0, int ct, ull acc[4][4])
{
    int kr0 = tid >> 5;          // 0..7
    int cq0 = (tid & 31) * 4;    // 0..124
    // prologue: fill buffer 0 (k-chunk 0)
    {
        const float* Wp = W + c0;
        *(float4*)(Bs + kr0*128 + cq0)      = *(const float4*)(Wp + (size_t)kr0*ldW + cq0);
        *(float4*)(Bs + (kr0+8)*128 + cq0)  = *(const float4*)(Wp + (size_t)(kr0+8)*ldW + cq0);
    }
    __syncthreads();
    for (int kc = 0; kc < NK; kc++){
        int cur = kc & 1;
        float4 st0, st1;
        bool pre = (kc + 1 < NK);
        if (pre){
            const float* Wp = W + (size_t)((kc+1)*16)*ldW + c0;
            st0 = *(const float4*)(Wp + (size_t)kr0*ldW + cq0);
            st1 = *(const float4*)(Wp + (size_t)(kr0+8)*ldW + cq0);
        }
        const float* Ak = AT + (size_t)(kc*16)*lda + r0;
        const float* Bb = Bs + cur*2048 + ct;
        #pragma unroll
        for (int kk = 0; kk < 16; kk++){
            const ull* ap = (const ull*)(Ak + kk*lda);
            ull a0 = ap[0], a1 = ap[1], a2 = ap[2], a3 = ap[3];
            const float* bp = Bb + kk*128;
            ull q0 = dup2(bp[0]), q1 = dup2(bp[32]), q2 = dup2(bp[64]), q3 = dup2(bp[96]);
            acc[0][0] = ffma2(a0, q0, acc[0][0]);
            acc[1][0] = ffma2(a1, q0, acc[1][0]);
            acc[2][0] = ffma2(a2, q0, acc[2][0]);
            acc[3][0] = ffma2(a3, q0, acc[3][0]);
            acc[0][1] = ffma2(a0, q1, acc[0][1]);
            acc[1][1] = ffma2(a1, q1, acc[1][1]);
            acc[2][1] = ffma2(a2, q1, acc[2][1]);
            acc[3][1] = ffma2(a3, q1, acc[3][1]);
            acc[0][2] = ffma2(a0, q2, acc[0][2]);
            acc[1][2] = ffma2(a1, q2, acc[1][2]);
            acc[2][2] = ffma2(a2, q2, acc[2][2]);
            acc[3][2] = ffma2(a3, q2, acc[3][2]);
            acc[0][3] = ffma2(a0, q3, acc[0][3]);
            acc[1][3] = ffma2(a1, q3, acc[1][3]);
            acc[2][3] = ffma2(a2, q3, acc[2][3]);
            acc[3][3] = ffma2(a3, q3, acc[3][3]);
        }
        if (pre){
            float* dst = Bs + (cur^1)*2048;
            *(float4*)(dst + kr0*128 + cq0)     = st0;
            *(float4*)(dst + (kr0+8)*128 + cq0) = st1;
        }
        __syncthreads();
    }
}

__global__ void __launch_bounds__(256,1) k_mlp(
    const float* __restrict__ b1v, const float* __restrict__ gamma,
    const float* __restrict__ beta, const float* __restrict__ W2,
    const float* __restrict__ b2v, float* __restrict__ out)
{
    extern __shared__ float sm[];
    float* As = sm;                     // 16384 floats
    float* Bs = sm + 16384;             // 4096 floats (also LN scratch)
    float* Xs = sm + 16384 + 4096;      // 512*66 floats

    int tid  = threadIdx.x;
    int warp = tid >> 5, ct = tid & 31;
    int r0   = warp * 8;
    int rowBase = blockIdx.x * 64;

    // ---- load A tile transposed into As[k][row] ----
    {
        int row = tid & 63, seg = tid >> 6;
        const float* src = g_omega + (size_t)(rowBase + row)*256 + seg*64;
        #pragma unroll
        for (int i = 0; i < 16; i++){
            float4 v = *(const float4*)(src + i*4);
            int k = seg*64 + i*4;
            As[(k+0)*64 + row] = v.x;
            As[(k+1)*64 + row] = v.y;
            As[(k+2)*64 + row] = v.z;
            As[(k+3)*64 + row] = v.w;
        }
    }
    __syncthreads();

    // ---- GEMM1: 4 col-chunks of 128, K=256 ----
    for (int cc = 0; cc < 4; cc++){
        int c0 = cc * 128;
        ull acc[4][4];
        #pragma unroll
        for (int i = 0; i < 4; i++)
            #pragma unroll
            for (int j = 0; j < 4; j++) acc[i][j] = 0ULL;

        gemm_chunk(As, 64, g_w1p, HIDN, 16, c0, Bs, tid, r0, ct, acc);

        // epilogue: + b1, store transposed to Xs[col][rowpair]
        #pragma unroll
        for (int j = 0; j < 4; j++){
            int col = c0 + j*32 + ct;
            ull bb = dup2(b1v[col]);
            #pragma unroll
            for (int i2 = 0; i2 < 4; i2++){
                *(ull*)(Xs + col*66 + r0 + i2*2) = add2(acc[i2][j], bb);
            }
        }
        __syncthreads();
    }

    // ---- LayerNorm + GELU (in place on Xs) ----
    {
        int r = tid & 63, q = tid >> 6;
        float s = 0.f, s2 = 0.f;
        for (int c = q*128; c < q*128 + 128; c++){
            float v = Xs[c*66 + r];
            s += v; s2 += v*v;
        }
        Bs[tid] = s; Bs[256 + tid] = s2;
        __syncthreads();
        if (q == 0){
            float S  = Bs[r] + Bs[64+r] + Bs[128+r] + Bs[192+r];
            float S2 = Bs[256+r] + Bs[320+r] + Bs[384+r] + Bs[448+r];
            float mu  = S * (1.f/512.f);
            float var = S2 * (1.f/512.f) - mu*mu;
            Bs[512 + r] = mu;
            Bs[576 + r] = rsqrtf(var + 1e-5f);
        }
        __syncthreads();
        float mu = Bs[512 + r], rs = Bs[576 + r];
        for (int c = q*128; c < q*128 + 128; c++){
            float v = Xs[c*66 + r];
            v = (v - mu) * rs * gamma[c] + beta[c];
            v = 0.5f * v * (1.f + erff(v * 0.70710678118654752f));
            Xs[c*66 + r] = v;
        }
        __syncthreads();
    }

    // ---- GEMM2: 2 col-chunks of 128, K=512 ----
    for (int cc = 0; cc < 2; cc++){
        int c0 = cc * 128;
        ull acc[4][4];
        #pragma unroll
        for (int i = 0; i < 4; i++)
            #pragma unroll
            for (int j = 0; j < 4; j++) acc[i][j] = 0ULL;

        gemm_chunk(Xs, 66, W2, OUTN, 32, c0, Bs, tid, r0, ct, acc);

        // epilogue: + b2, write to global (coalesced STG.32)
        #pragma unroll
        for (int j = 0; j < 4; j++){
            int col = c0 + j*32 + ct;
            float bias = b2v[col];
            #pragma unroll
            for (int i2 = 0; i2 < 4; i2++){
                float2 v = unpk(acc[i2][j]);
                size_t rg = (size_t)(rowBase + r0 + i2*2);
                out[rg*OUTN + col]       = v.x + bias;
                out[(rg+1)*OUTN + col]   = v.y + bias;
            }
        }
        __syncthreads();
    }
}

// ---------------- launch ----------------
extern "C" void kernel_launch(void* const* d_in, const int* in_sizes, int n_in,
                              void* d_out, int out_size)
{
    const int* edges = (const int*)d_in[0];
    // num_nodes may or may not be materialized as a scalar input at slot 1
    int p = (in_sizes[1] <= 2) ? 2 : 1;
    const float* poh   = (const float*)d_in[p+0];
    const float* emb   = (const float*)d_in[p+1];
    const float* W1    = (const float*)d_in[p+2];
    const float* b1    = (const float*)d_in[p+3];
    const float* gamma = (const float*)d_in[p+4];
    const float* beta  = (const float*)d_in[p+5];
    const float* W2    = (const float*)d_in[p+6];
    const float* b2    = (const float*)d_in[p+7];
    float* out = (float*)d_out;

    cudaFuncSetAttribute(k_mlp, cudaFuncAttributeMaxDynamicSharedMemorySize, SMEM_BYTES);

    k_zero_cnt<<<(NROW + 255)/256, 256>>>();
    k_build  <<<(Bg*Eg + 255)/256, 256>>>(edges);
    k_argmax <<<(Nn + 255)/256, 256>>>(poh);
    k_gather <<<(Nn*16 + 255)/256, 256>>>(emb);
    k_permw1 <<<(HOPSN*Dd*HIDN + 255)/256, 256>>>(W1);
    for (int h = 1; h <= HOPSN; h++)
        k_hop<<<(NROW*16 + 255)/256, 256>>>(h);
    k_mlp<<<NROW/64, 256, SMEM_BYTES>>>(b1, gamma, beta, W2, b2, out);
}

// round 4
// speedup vs baseline: 1.6019x; 1.6012x over previous
#include <cuda_runtime.h>
#include <cuda_bf16.h>
#include <math.h>
#include <stdint.h>

#define Bg 8
#define Nn 20000
#define Eg 320000
#define Cc 128
#define Dd 64
#define CAP 96
#define NROW (Bg*Nn)

// ---------------- device scratch ----------------
__device__ int   g_cnt[NROW];
__device__ int   g_adj[(size_t)NROW*CAP];
__device__ int   g_idx[Nn];
__device__ float g_init[Nn*Dd];
__device__ float g_omega[(size_t)NROW*256];
__device__ __nv_bfloat16 g_w1hi[512*256];
__device__ __nv_bfloat16 g_w1lo[512*256];
__device__ __nv_bfloat16 g_w2hi[256*512];
__device__ __nv_bfloat16 g_w2lo[256*512];

// ---------------- graph kernels ----------------
__global__ void k_zero_cnt(){
    int i = blockIdx.x*blockDim.x + threadIdx.x;
    if (i < NROW) g_cnt[i] = 0;
}
__global__ void k_build(const int* __restrict__ edges){
    int i = blockIdx.x*blockDim.x + threadIdx.x;
    if (i >= Bg*Eg) return;
    int b = i / Eg, e = i % Eg;
    const int* eb = edges + (size_t)b*2*Eg;
    int row = b*Nn + eb[e];
    int c = eb[Eg + e];
    int slot = atomicAdd(&g_cnt[row], 1);
    if (slot < CAP) g_adj[(size_t)row*CAP + slot] = c;
}
__global__ void k_argmax(const float* __restrict__ poh){
    int n = blockIdx.x*blockDim.x + threadIdx.x;
    if (n >= Nn) return;
    float best = poh[n]; int bi = 0;
    #pragma unroll 4
    for (int c = 1; c < Cc; c++){
        float v = poh[(size_t)c*Nn + n];
        if (v > best){ best = v; bi = c; }
    }
    g_idx[n] = bi;
}
__global__ void k_gather(const float* __restrict__ emb){
    int i = blockIdx.x*blockDim.x + threadIdx.x;
    if (i >= Nn*16) return;
    int n = i >> 4, l = i & 15;
    float4 v = *(const float4*)(emb + (size_t)g_idx[n]*Dd + l*4);
    *(float4*)(g_init + (size_t)n*Dd + l*4) = v;
}
__global__ void k_hop(int hop){
    int gid = blockIdx.x*blockDim.x + threadIdx.x;
    int row = gid >> 4, lane = gid & 15;
    if (row >= NROW) return;
    int b = row / Nn;
    const float* src; int rs;
    if (hop == 1){ src = g_init + lane*4; rs = Dd; }
    else         { src = g_omega + (size_t)b*Nn*256 + (hop-2)*Dd + lane*4; rs = 256; }
    int cnt = g_cnt[row]; if (cnt > CAP) cnt = CAP;
    const int* adj = g_adj + (size_t)row*CAP;
    float4 s0 = make_float4(0.f,0.f,0.f,0.f), s1 = make_float4(0.f,0.f,0.f,0.f);
    int j = 0;
    for (; j + 2 <= cnt; j += 2){
        int c0 = adj[j], c1 = adj[j+1];
        float4 v0 = *(const float4*)(src + (size_t)c0*rs);
        float4 v1 = *(const float4*)(src + (size_t)c1*rs);
        s0.x += v0.x; s0.y += v0.y; s0.z += v0.z; s0.w += v0.w;
        s1.x += v1.x; s1.y += v1.y; s1.z += v1.z; s1.w += v1.w;
    }
    if (j < cnt){
        float4 v = *(const float4*)(src + (size_t)adj[j]*rs);
        s0.x += v.x; s0.y += v.y; s0.z += v.z; s0.w += v.w;
    }
    float4 r = make_float4(s0.x+s1.x, s0.y+s1.y, s0.z+s1.z, s0.w+s1.w);
    *(float4*)(g_omega + (size_t)row*256 + (hop-1)*Dd + lane*4) = r;
}

// ---------------- weight split/blocking ----------------
// W1 blocks: nchunk(2) x kchunk(16) blocks of [256 n][16 k] halves.
// logical k = h*64+d maps to W1 row (d*4+h)  (matches stack(...,-1).reshape)
__global__ void k_convW1(const float* __restrict__ W1){
    int i = blockIdx.x*256 + threadIdx.x;
    if (i >= 256*512) return;
    int k = i >> 9, n = i & 511;
    int d = k & 63, h = k >> 6;
    float v = W1[(size_t)(d*4 + h)*512 + n];
    __nv_bfloat16 hb = __float2bfloat16(v);
    float lo = v - __bfloat162float(hb);
    int nc = n >> 8, nn = n & 255, kc = k >> 4, kk = k & 15;
    int off = ((nc*16 + kc)*256 + nn)*16 + kk;
    g_w1hi[off] = hb; g_w1lo[off] = __float2bfloat16(lo);
}
// W2 blocks: kchunk(32) blocks of [256 n][16 k]
__global__ void k_convW2(const float* __restrict__ W2){
    int i = blockIdx.x*256 + threadIdx.x;
    if (i >= 512*256) return;
    int k = i >> 8, n = i & 255;
    float v = W2[(size_t)k*256 + n];
    __nv_bfloat16 hb = __float2bfloat16(v);
    float lo = v - __bfloat162float(hb);
    int kc = k >> 4, kk = k & 15;
    int off = (kc*256 + n)*16 + kk;
    g_w2hi[off] = hb; g_w2lo[off] = __float2bfloat16(lo);
}

// ---------------- fused MLP (mma.sync bf16 3-term split) ----------------
#define AST 260
#define XST 516
#define OFF_A  0
#define OFF_X  (64*AST*4)                 // 66560
#define OFF_BH (OFF_X + 64*XST*4)         // 198656
#define OFF_BL (OFF_BH + 8192)            // 206848
#define OFF_SC (OFF_BL + 8192)            // 215040
#define SMEM_TOTAL (OFF_SC + 4096)        // 219136

__device__ __forceinline__ void mma_bf16(float* d, const unsigned* a, unsigned b0, unsigned b1){
    asm volatile(
      "mma.sync.aligned.m16n8k16.row.col.f32.bf16.bf16.f32 "
      "{%0,%1,%2,%3},{%4,%5,%6,%7},{%8,%9},{%0,%1,%2,%3};"
      : "+f"(d[0]), "+f"(d[1]), "+f"(d[2]), "+f"(d[3])
      : "r"(a[0]), "r"(a[1]), "r"(a[2]), "r"(a[3]), "r"(b0), "r"(b1));
}
__device__ __forceinline__ void split2(float x, float y, unsigned &hi, unsigned &lo){
    __nv_bfloat162 h = __floats2bfloat162_rn(x, y);
    float lx = x - __bfloat162float(__low2bfloat16(h));
    float ly = y - __bfloat162float(__high2bfloat16(h));
    __nv_bfloat162 l = __floats2bfloat162_rn(lx, ly);
    hi = *reinterpret_cast<unsigned*>(&h);
    lo = *reinterpret_cast<unsigned*>(&l);
}

// one N=256 pass: acc[4 m][4 n][4], A from smem fp32 (split at frag time),
// B hi/lo streamed global->smem with register-prefetch double buffering
template<int NK>
__device__ __forceinline__ void gemm_pass(
    const float* Asm, int ast,
    const __nv_bfloat16* gBh, const __nv_bfloat16* gBl,
    char* sm, int tid, int w, int gid, int tig,
    float acc[4][4][4])
{
    __nv_bfloat16* Bh = (__nv_bfloat16*)(sm + OFF_BH);
    __nv_bfloat16* Bl = (__nv_bfloat16*)(sm + OFF_BL);
    {
        const uint4* ph = (const uint4*)gBh;
        const uint4* pl = (const uint4*)gBl;
        ((uint4*)Bh)[tid] = ph[tid]; ((uint4*)Bh)[tid+256] = ph[tid+256];
        ((uint4*)Bl)[tid] = pl[tid]; ((uint4*)Bl)[tid+256] = pl[tid+256];
    }
    __syncthreads();
    for (int kc = 0; kc < NK; kc++){
        uint4 pf0, pf1, pf2, pf3;
        bool pre = (kc + 1 < NK);
        if (pre){
            const uint4* ph = (const uint4*)(gBh + (kc+1)*4096);
            const uint4* pl = (const uint4*)(gBl + (kc+1)*4096);
            pf0 = ph[tid]; pf1 = ph[tid+256]; pf2 = pl[tid]; pf3 = pl[tid+256];
        }
        int k0 = kc*16;
        unsigned ah[4][4], al[4][4];
        #pragma unroll
        for (int i = 0; i < 4; i++){
            const float* r0 = Asm + (i*16 + gid)*ast + k0 + tig*2;
            const float* r8 = r0 + 8*ast;
            float2 f0 = *(const float2*)r0,  f1 = *(const float2*)(r0 + 8);
            float2 f2 = *(const float2*)r8,  f3 = *(const float2*)(r8 + 8);
            split2(f0.x, f0.y, ah[i][0], al[i][0]);
            split2(f2.x, f2.y, ah[i][1], al[i][1]);
            split2(f1.x, f1.y, ah[i][2], al[i][2]);
            split2(f3.x, f3.y, ah[i][3], al[i][3]);
        }
        #pragma unroll
        for (int j = 0; j < 4; j++){
            int brow = w*32 + j*8 + gid;
            unsigned bh0 = *(const unsigned*)(Bh + brow*16 + tig*2);
            unsigned bh1 = *(const unsigned*)(Bh + brow*16 + tig*2 + 8);
            unsigned bl0 = *(const unsigned*)(Bl + brow*16 + tig*2);
            unsigned bl1 = *(const unsigned*)(Bl + brow*16 + tig*2 + 8);
            #pragma unroll
            for (int i = 0; i < 4; i++){
                mma_bf16(acc[i][j], ah[i], bh0, bh1);
                mma_bf16(acc[i][j], ah[i], bl0, bl1);
                mma_bf16(acc[i][j], al[i], bh0, bh1);
            }
        }
        __syncthreads();
        if (pre){
            ((uint4*)Bh)[tid] = pf0; ((uint4*)Bh)[tid+256] = pf1;
            ((uint4*)Bl)[tid] = pf2; ((uint4*)Bl)[tid+256] = pf3;
            __syncthreads();
        }
    }
}

__global__ void __launch_bounds__(256,1) k_mlp(
    const float* __restrict__ b1v, const float* __restrict__ gamma,
    const float* __restrict__ beta, const float* __restrict__ b2v,
    float* __restrict__ out)
{
    extern __shared__ char sm[];
    float* As = (float*)(sm + OFF_A);
    float* Xs = (float*)(sm + OFF_X);
    float* SC = (float*)(sm + OFF_SC);

    int tid = threadIdx.x;
    int lane = tid & 31, w = tid >> 5;
    int gid = lane >> 2, tig = lane & 3;
    int rowBase = blockIdx.x * 64;

    // load A tile [64][256] fp32 (row-major copy, coalesced)
    for (int i = tid; i < 4096; i += 256){
        int r = i >> 6, c = (i & 63)*4;
        float4 v = *(const float4*)(g_omega + (size_t)(rowBase + r)*256 + c);
        *(float4*)(As + r*AST + c) = v;
    }
    __syncthreads();

    float acc[4][4][4];

    // ---- GEMM1: X = A @ W1p, two 256-col chunks, K=256 ----
    for (int nc = 0; nc < 2; nc++){
        #pragma unroll
        for (int i = 0; i < 4; i++)
            #pragma unroll
            for (int j = 0; j < 4; j++)
                #pragma unroll
                for (int q = 0; q < 4; q++) acc[i][j][q] = 0.f;

        gemm_pass<16>(As, AST, g_w1hi + nc*16*4096, g_w1lo + nc*16*4096,
                      sm, tid, w, gid, tig, acc);

        // epilogue: + b1, store fp32 to Xs
        #pragma unroll
        for (int j = 0; j < 4; j++){
            int col = nc*256 + w*32 + j*8 + tig*2;
            float ba = __ldg(b1v + col), bb = __ldg(b1v + col + 1);
            #pragma unroll
            for (int i = 0; i < 4; i++){
                int r = i*16 + gid;
                *(float2*)(Xs + r*XST + col)     = make_float2(acc[i][j][0] + ba, acc[i][j][1] + bb);
                *(float2*)(Xs + (r+8)*XST + col) = make_float2(acc[i][j][2] + ba, acc[i][j][3] + bb);
            }
        }
        __syncthreads();
    }

    // ---- LayerNorm + GELU (in place on Xs) ----
    {
        int r = tid & 63, q = tid >> 6;
        const float* xr = Xs + r*XST + q*128;
        float s = 0.f, s2 = 0.f;
        #pragma unroll
        for (int i = 0; i < 32; i++){
            float4 v = *(const float4*)(xr + i*4);
            s  += v.x + v.y + v.z + v.w;
            s2 += v.x*v.x + v.y*v.y + v.z*v.z + v.w*v.w;
        }
        SC[q*64 + r] = s; SC[256 + q*64 + r] = s2;
        __syncthreads();
        if (tid < 64){
            float S  = SC[tid] + SC[64+tid] + SC[128+tid] + SC[192+tid];
            float S2 = SC[256+tid] + SC[320+tid] + SC[384+tid] + SC[448+tid];
            float mu  = S * (1.f/512.f);
            float var = S2 * (1.f/512.f) - mu*mu;
            SC[512 + tid] = mu;
            SC[576 + tid] = rsqrtf(var + 1e-5f);
        }
        __syncthreads();
        float mu = SC[512 + r], rs = SC[576 + r];
        float* xw = Xs + r*XST + q*128;
        #pragma unroll
        for (int i = 0; i < 32; i++){
            float4 v = *(float4*)(xw + i*4);
            int c = q*128 + i*4;
            v.x = (v.x - mu)*rs*__ldg(gamma+c)   + __ldg(beta+c);
            v.y = (v.y - mu)*rs*__ldg(gamma+c+1) + __ldg(beta+c+1);
            v.z = (v.z - mu)*rs*__ldg(gamma+c+2) + __ldg(beta+c+2);
            v.w = (v.w - mu)*rs*__ldg(gamma+c+3) + __ldg(beta+c+3);
            v.x = 0.5f*v.x*(1.f + erff(v.x*0.70710678118654752f));
            v.y = 0.5f*v.y*(1.f + erff(v.y*0.70710678118654752f));
            v.z = 0.5f*v.z*(1.f + erff(v.z*0.70710678118654752f));
            v.w = 0.5f*v.w*(1.f + erff(v.w*0.70710678118654752f));
            *(float4*)(xw + i*4) = v;
        }
        __syncthreads();
    }

    // ---- GEMM2: OUT = X @ W2, one 256-col chunk, K=512 ----
    #pragma unroll
    for (int i = 0; i < 4; i++)
        #pragma unroll
        for (int j = 0; j < 4; j++)
            #pragma unroll
            for (int q = 0; q < 4; q++) acc[i][j][q] = 0.f;

    gemm_pass<32>(Xs, XST, g_w2hi, g_w2lo, sm, tid, w, gid, tig, acc);

    // epilogue: + b2, write out
    #pragma unroll
    for (int j = 0; j < 4; j++){
        int col = w*32 + j*8 + tig*2;
        float ba = __ldg(b2v + col), bb = __ldg(b2v + col + 1);
        #pragma unroll
        for (int i = 0; i < 4; i++){
            int r = i*16 + gid;
            *(float2*)(out + (size_t)(rowBase + r)*256 + col)   = make_float2(acc[i][j][0] + ba, acc[i][j][1] + bb);
            *(float2*)(out + (size_t)(rowBase + r + 8)*256 + col) = make_float2(acc[i][j][2] + ba, acc[i][j][3] + bb);
        }
    }
}

// ---------------- launch ----------------
extern "C" void kernel_launch(void* const* d_in, const int* in_sizes, int n_in,
                              void* d_out, int out_size)
{
    const int* edges = (const int*)d_in[0];
    int p = (in_sizes[1] <= 2) ? 2 : 1;
    const float* poh   = (const float*)d_in[p+0];
    const float* emb   = (const float*)d_in[p+1];
    const float* W1    = (const float*)d_in[p+2];
    const float* b1    = (const float*)d_in[p+3];
    const float* gamma = (const float*)d_in[p+4];
    const float* beta  = (const float*)d_in[p+5];
    const float* W2    = (const float*)d_in[p+6];
    const float* b2    = (const float*)d_in[p+7];
    float* out = (float*)d_out;

    cudaFuncSetAttribute(k_mlp, cudaFuncAttributeMaxDynamicSharedMemorySize, SMEM_TOTAL);

    k_zero_cnt<<<(NROW + 255)/256, 256>>>();
    k_build  <<<(Bg*Eg + 255)/256, 256>>>(edges);
    k_argmax <<<(Nn + 255)/256, 256>>>(poh);
    k_gather <<<(Nn*16 + 255)/256, 256>>>(emb);
    k_convW1 <<<512, 256>>>(W1);
    k_convW2 <<<512, 256>>>(W2);
    for (int h = 1; h <= 4; h++)
        k_hop<<<(NROW*16 + 255)/256, 256>>>(h);
    k_mlp<<<NROW/64, 256, SMEM_TOTAL>>>(b1, gamma, beta, b2, out);
}

// round 5
// speedup vs baseline: 1.6956x; 1.0585x over previous
#include <cuda_runtime.h>
#include <cuda_bf16.h>
#include <math.h>
#include <stdint.h>

#define Bg 8
#define Nn 20000
#define Eg 320000
#define Cc 128
#define Dd 64
#define CAP 96
#define NROW (Bg*Nn)

// ---------------- device scratch ----------------
__device__ int   g_cnt[NROW];
__device__ int   g_adj[(size_t)NROW*CAP];
__device__ int   g_idx[Nn];
__device__ float g_init[Nn*Dd];
__device__ float g_omega[(size_t)NROW*256];
__device__ __nv_bfloat16 g_w1hi[512*256];
__device__ __nv_bfloat16 g_w1lo[512*256];
__device__ __nv_bfloat16 g_w2hi[256*512];
__device__ __nv_bfloat16 g_w2lo[256*512];

// ---------------- graph kernels (unchanged, proven) ----------------
__global__ void k_zero_cnt(){
    int i = blockIdx.x*blockDim.x + threadIdx.x;
    if (i < NROW) g_cnt[i] = 0;
}
__global__ void k_build(const int* __restrict__ edges){
    int i = blockIdx.x*blockDim.x + threadIdx.x;
    if (i >= Bg*Eg) return;
    int b = i / Eg, e = i % Eg;
    const int* eb = edges + (size_t)b*2*Eg;
    int row = b*Nn + eb[e];
    int c = eb[Eg + e];
    int slot = atomicAdd(&g_cnt[row], 1);
    if (slot < CAP) g_adj[(size_t)row*CAP + slot] = c;
}
__global__ void k_argmax(const float* __restrict__ poh){
    int n = blockIdx.x*blockDim.x + threadIdx.x;
    if (n >= Nn) return;
    float best = poh[n]; int bi = 0;
    #pragma unroll 4
    for (int c = 1; c < Cc; c++){
        float v = poh[(size_t)c*Nn + n];
        if (v > best){ best = v; bi = c; }
    }
    g_idx[n] = bi;
}
__global__ void k_gather(const float* __restrict__ emb){
    int i = blockIdx.x*blockDim.x + threadIdx.x;
    if (i >= Nn*16) return;
    int n = i >> 4, l = i & 15;
    float4 v = *(const float4*)(emb + (size_t)g_idx[n]*Dd + l*4);
    *(float4*)(g_init + (size_t)n*Dd + l*4) = v;
}
__global__ void k_hop(int hop){
    int gid = blockIdx.x*blockDim.x + threadIdx.x;
    int row = gid >> 4, lane = gid & 15;
    if (row >= NROW) return;
    int b = row / Nn;
    const float* src; int rs;
    if (hop == 1){ src = g_init + lane*4; rs = Dd; }
    else         { src = g_omega + (size_t)b*Nn*256 + (hop-2)*Dd + lane*4; rs = 256; }
    int cnt = g_cnt[row]; if (cnt > CAP) cnt = CAP;
    const int* adj = g_adj + (size_t)row*CAP;
    float4 s0 = make_float4(0.f,0.f,0.f,0.f), s1 = make_float4(0.f,0.f,0.f,0.f);
    int j = 0;
    for (; j + 2 <= cnt; j += 2){
        int c0 = adj[j], c1 = adj[j+1];
        float4 v0 = *(const float4*)(src + (size_t)c0*rs);
        float4 v1 = *(const float4*)(src + (size_t)c1*rs);
        s0.x += v0.x; s0.y += v0.y; s0.z += v0.z; s0.w += v0.w;
        s1.x += v1.x; s1.y += v1.y; s1.z += v1.z; s1.w += v1.w;
    }
    if (j < cnt){
        float4 v = *(const float4*)(src + (size_t)adj[j]*rs);
        s0.x += v.x; s0.y += v.y; s0.z += v.z; s0.w += v.w;
    }
    float4 r = make_float4(s0.x+s1.x, s0.y+s1.y, s0.z+s1.z, s0.w+s1.w);
    *(float4*)(g_omega + (size_t)row*256 + (hop-1)*Dd + lane*4) = r;
}

// ---------------- weight split/blocking (unchanged) ----------------
__global__ void k_convW1(const float* __restrict__ W1){
    int i = blockIdx.x*256 + threadIdx.x;
    if (i >= 256*512) return;
    int k = i >> 9, n = i & 511;
    int d = k & 63, h = k >> 6;
    float v = W1[(size_t)(d*4 + h)*512 + n];
    __nv_bfloat16 hb = __float2bfloat16(v);
    float lo = v - __bfloat162float(hb);
    int nc = n >> 8, nn = n & 255, kc = k >> 4, kk = k & 15;
    int off = ((nc*16 + kc)*256 + nn)*16 + kk;
    g_w1hi[off] = hb; g_w1lo[off] = __float2bfloat16(lo);
}
__global__ void k_convW2(const float* __restrict__ W2){
    int i = blockIdx.x*256 + threadIdx.x;
    if (i >= 512*256) return;
    int k = i >> 8, n = i & 255;
    float v = W2[(size_t)k*256 + n];
    __nv_bfloat16 hb = __float2bfloat16(v);
    float lo = v - __bfloat162float(hb);
    int kc = k >> 4, kk = k & 15;
    int off = (kc*256 + n)*16 + kk;
    g_w2hi[off] = hb; g_w2lo[off] = __float2bfloat16(lo);
}

// ---------------- fused MLP (ldmatrix + mma.sync, pre-split operands) ----------------
#define AST2 264      // A smem k-stride (elems): 528B rows -> conflict-free ldmatrix
#define XST2 520      // X smem k-stride: 1040B rows
#define BST  24       // B smem k-stride: 48B rows -> conflict-free ldmatrix
#define OFF_AH 0
#define OFF_AL 33792
#define OFF_XH 67584
#define OFF_XL 134144
#define OFF_BH 200704
#define OFF_BL 212992
#define OFF_SC 225280
#define SMEM_TOTAL 229376

__device__ __forceinline__ uint32_t smem_u32(const void* p){
    uint32_t a;
    asm("{ .reg .u64 t; cvta.to.shared.u64 t, %1; cvt.u32.u64 %0, t; }" : "=r"(a) : "l"(p));
    return a;
}
__device__ __forceinline__ void ldmx4(unsigned* r, uint32_t addr){
    asm volatile("ldmatrix.sync.aligned.m8n8.x4.shared.b16 {%0,%1,%2,%3}, [%4];"
        : "=r"(r[0]), "=r"(r[1]), "=r"(r[2]), "=r"(r[3]) : "r"(addr));
}
__device__ __forceinline__ void mma_bf16(float* d, const unsigned* a, unsigned b0, unsigned b1){
    asm volatile(
      "mma.sync.aligned.m16n8k16.row.col.f32.bf16.bf16.f32 "
      "{%0,%1,%2,%3},{%4,%5,%6,%7},{%8,%9},{%0,%1,%2,%3};"
      : "+f"(d[0]), "+f"(d[1]), "+f"(d[2]), "+f"(d[3])
      : "r"(a[0]), "r"(a[1]), "r"(a[2]), "r"(a[3]), "r"(b0), "r"(b1));
}
__device__ __forceinline__ void split2(float x, float y, unsigned &hi, unsigned &lo){
    __nv_bfloat162 h = __floats2bfloat162_rn(x, y);
    float lx = x - __bfloat162float(__low2bfloat16(h));
    float ly = y - __bfloat162float(__high2bfloat16(h));
    __nv_bfloat162 l = __floats2bfloat162_rn(lx, ly);
    hi = *reinterpret_cast<unsigned*>(&h);
    lo = *reinterpret_cast<unsigned*>(&l);
}
__device__ __forceinline__ float2 rec2(unsigned h, unsigned l){
    __nv_bfloat162 hb = *reinterpret_cast<__nv_bfloat162*>(&h);
    __nv_bfloat162 lb = *reinterpret_cast<__nv_bfloat162*>(&l);
    return make_float2(__low2float(hb) + __low2float(lb),
                       __high2float(hb) + __high2float(lb));
}

// one N=256 pass over pre-split A (smem bf16 hi/lo) x streamed B blocks
template<int NK, int ASTRIDE>
__device__ __forceinline__ void gemm_pass(
    uint32_t aHi, uint32_t aLo,
    const __nv_bfloat16* __restrict__ gBh, const __nv_bfloat16* __restrict__ gBl,
    char* sm, uint32_t smb, int tid, int w, float acc[4][4][4])
{
    int lane = tid & 31;
    int arow = lane & 15, akh = (lane >> 4) * 8;
    int brow = (lane & 7) + ((lane >> 4) & 1) * 8;
    int bko  = ((lane >> 3) & 1) * 8;
    int i0 = tid, i1 = tid + 256;
    uint32_t s0 = (uint32_t)(((i0 >> 1)*BST + (i0 & 1)*8)*2);
    uint32_t s1 = (uint32_t)(((i1 >> 1)*BST + (i1 & 1)*8)*2);
    {
        const uint4* ph = (const uint4*)gBh;
        const uint4* pl = (const uint4*)gBl;
        uint4 c0 = ph[i0], c1 = ph[i1], c2 = pl[i0], c3 = pl[i1];
        *(uint4*)(sm + OFF_BH + s0) = c0; *(uint4*)(sm + OFF_BH + s1) = c1;
        *(uint4*)(sm + OFF_BL + s0) = c2; *(uint4*)(sm + OFF_BL + s1) = c3;
    }
    __syncthreads();
    for (int kc = 0; kc < NK; kc++){
        uint4 p0, p1, p2, p3;
        bool pre = (kc + 1 < NK);
        if (pre){
            const uint4* ph = (const uint4*)(gBh + (size_t)(kc+1)*4096);
            const uint4* pl = (const uint4*)(gBl + (size_t)(kc+1)*4096);
            p0 = ph[i0]; p1 = ph[i1]; p2 = pl[i0]; p3 = pl[i1];
        }
        unsigned ah[4][4], al[4][4];
        uint32_t abase = (uint32_t)((arow*ASTRIDE + kc*16 + akh)*2);
        #pragma unroll
        for (int i = 0; i < 4; i++){
            ldmx4(ah[i], aHi + abase + (uint32_t)(i*16*ASTRIDE*2));
            ldmx4(al[i], aLo + abase + (uint32_t)(i*16*ASTRIDE*2));
        }
        unsigned bh[2][4], bl[2][4];
        #pragma unroll
        for (int jj = 0; jj < 2; jj++){
            uint32_t boff = (uint32_t)((((w*32 + jj*16) + brow)*BST + bko)*2);
            ldmx4(bh[jj], smb + OFF_BH + boff);
            ldmx4(bl[jj], smb + OFF_BL + boff);
        }
        #pragma unroll
        for (int j = 0; j < 4; j++){
            unsigned b0h = bh[j>>1][(j&1)*2], b1h = bh[j>>1][(j&1)*2+1];
            unsigned b0l = bl[j>>1][(j&1)*2], b1l = bl[j>>1][(j&1)*2+1];
            #pragma unroll
            for (int i = 0; i < 4; i++){
                mma_bf16(acc[i][j], ah[i], b0h, b1h);
                mma_bf16(acc[i][j], ah[i], b0l, b1l);
                mma_bf16(acc[i][j], al[i], b0h, b1h);
            }
        }
        __syncthreads();
        if (pre){
            *(uint4*)(sm + OFF_BH + s0) = p0; *(uint4*)(sm + OFF_BH + s1) = p1;
            *(uint4*)(sm + OFF_BL + s0) = p2; *(uint4*)(sm + OFF_BL + s1) = p3;
            __syncthreads();
        }
    }
}

__global__ void __launch_bounds__(256,1) k_mlp(
    const float* __restrict__ b1v, const float* __restrict__ gamma,
    const float* __restrict__ beta, const float* __restrict__ b2v,
    float* __restrict__ out)
{
    extern __shared__ char sm[];
    uint32_t smb = smem_u32(sm);
    float* SC = (float*)(sm + OFF_SC);

    int tid = threadIdx.x;
    int lane = tid & 31, w = tid >> 5;
    int gid = lane >> 2, tig = lane & 3;
    int rowBase = blockIdx.x * 64;

    // ---- load A tile [64][256], split fp32 -> bf16 hi/lo into smem ----
    for (int i = tid; i < 4096; i += 256){
        int r = i >> 6, c = (i & 63)*4;
        float4 v = *(const float4*)(g_omega + (size_t)(rowBase + r)*256 + c);
        unsigned h0, l0, h1, l1;
        split2(v.x, v.y, h0, l0);
        split2(v.z, v.w, h1, l1);
        *(uint2*)(sm + OFF_AH + (size_t)(r*AST2 + c)*2) = make_uint2(h0, h1);
        *(uint2*)(sm + OFF_AL + (size_t)(r*AST2 + c)*2) = make_uint2(l0, l1);
    }
    __syncthreads();

    float acc[4][4][4];

    // ---- GEMM1: X = A @ W1p, two 256-col chunks, K=256 ----
    for (int nc = 0; nc < 2; nc++){
        #pragma unroll
        for (int i = 0; i < 4; i++)
            #pragma unroll
            for (int j = 0; j < 4; j++)
                #pragma unroll
                for (int q = 0; q < 4; q++) acc[i][j][q] = 0.f;

        gemm_pass<16, AST2>(smb + OFF_AH, smb + OFF_AL,
                            g_w1hi + (size_t)nc*16*4096, g_w1lo + (size_t)nc*16*4096,
                            sm, smb, tid, w, acc);

        // epilogue: + b1, split to bf16 hi/lo, store to X smem
        #pragma unroll
        for (int j = 0; j < 4; j++){
            int col = nc*256 + w*32 + j*8 + tig*2;
            float ba = __ldg(b1v + col), bb = __ldg(b1v + col + 1);
            #pragma unroll
            for (int i = 0; i < 4; i++){
                int r = i*16 + gid;
                unsigned h, l;
                split2(acc[i][j][0] + ba, acc[i][j][1] + bb, h, l);
                *(unsigned*)(sm + OFF_XH + (size_t)(r*XST2 + col)*2) = h;
                *(unsigned*)(sm + OFF_XL + (size_t)(r*XST2 + col)*2) = l;
                split2(acc[i][j][2] + ba, acc[i][j][3] + bb, h, l);
                *(unsigned*)(sm + OFF_XH + (size_t)((r+8)*XST2 + col)*2) = h;
                *(unsigned*)(sm + OFF_XL + (size_t)((r+8)*XST2 + col)*2) = l;
            }
        }
        __syncthreads();
    }

    // ---- LayerNorm + GELU on X (hi/lo reconstruct, in place) ----
    {
        int r = tid & 63, q = tid >> 6;
        char* xh = sm + OFF_XH + (size_t)(r*XST2 + q*128)*2;
        char* xl = sm + OFF_XL + (size_t)(r*XST2 + q*128)*2;
        float s = 0.f, s2 = 0.f;
        #pragma unroll
        for (int i = 0; i < 16; i++){
            uint4 hv = *(uint4*)(xh + i*16);
            uint4 lv = *(uint4*)(xl + i*16);
            float2 e;
            e = rec2(hv.x, lv.x); s += e.x + e.y; s2 += e.x*e.x + e.y*e.y;
            e = rec2(hv.y, lv.y); s += e.x + e.y; s2 += e.x*e.x + e.y*e.y;
            e = rec2(hv.z, lv.z); s += e.x + e.y; s2 += e.x*e.x + e.y*e.y;
            e = rec2(hv.w, lv.w); s += e.x + e.y; s2 += e.x*e.x + e.y*e.y;
        }
        SC[q*64 + r] = s; SC[256 + q*64 + r] = s2;
        __syncthreads();
        if (tid < 64){
            float S  = SC[tid] + SC[64+tid] + SC[128+tid] + SC[192+tid];
            float S2 = SC[256+tid] + SC[320+tid] + SC[384+tid] + SC[448+tid];
            float mu  = S * (1.f/512.f);
            float var = S2 * (1.f/512.f) - mu*mu;
            SC[512 + tid] = mu;
            SC[576 + tid] = rsqrtf(var + 1e-5f);
        }
        __syncthreads();
        float mu = SC[512 + r], rsg = SC[576 + r];
        #pragma unroll
        for (int i = 0; i < 16; i++){
            uint4 hv = *(uint4*)(xh + i*16);
            uint4 lv = *(uint4*)(xl + i*16);
            unsigned hw[4], lw[4];
            unsigned* hvp = (unsigned*)&hv;
            unsigned* lvp = (unsigned*)&lv;
            #pragma unroll
            for (int t = 0; t < 4; t++){
                float2 e = rec2(hvp[t], lvp[t]);
                int c = q*128 + i*8 + t*2;
                float g0 = __ldg(gamma + c), g1 = __ldg(gamma + c + 1);
                float be0 = __ldg(beta + c), be1 = __ldg(beta + c + 1);
                e.x = (e.x - mu)*rsg*g0 + be0;
                e.y = (e.y - mu)*rsg*g1 + be1;
                e.x = 0.5f*e.x*(1.f + erff(e.x*0.70710678118654752f));
                e.y = 0.5f*e.y*(1.f + erff(e.y*0.70710678118654752f));
                split2(e.x, e.y, hw[t], lw[t]);
            }
            *(uint4*)(xh + i*16) = make_uint4(hw[0], hw[1], hw[2], hw[3]);
            *(uint4*)(xl + i*16) = make_uint4(lw[0], lw[1], lw[2], lw[3]);
        }
        __syncthreads();
    }

    // ---- GEMM2: OUT = X @ W2, one 256-col chunk, K=512 ----
    #pragma unroll
    for (int i = 0; i < 4; i++)
        #pragma unroll
        for (int j = 0; j < 4; j++)
            #pragma unroll
            for (int q = 0; q < 4; q++) acc[i][j][q] = 0.f;

    gemm_pass<32, XST2>(smb + OFF_XH, smb + OFF_XL, g_w2hi, g_w2lo,
                        sm, smb, tid, w, acc);

    // epilogue: + b2, write out
    #pragma unroll
    for (int j = 0; j < 4; j++){
        int col = w*32 + j*8 + tig*2;
        float ba = __ldg(b2v + col), bb = __ldg(b2v + col + 1);
        #pragma unroll
        for (int i = 0; i < 4; i++){
            int r = i*16 + gid;
            *(float2*)(out + (size_t)(rowBase + r)*256 + col)     = make_float2(acc[i][j][0] + ba, acc[i][j][1] + bb);
            *(float2*)(out + (size_t)(rowBase + r + 8)*256 + col) = make_float2(acc[i][j][2] + ba, acc[i][j][3] + bb);
        }
    }
}

// ---------------- launch ----------------
extern "C" void kernel_launch(void* const* d_in, const int* in_sizes, int n_in,
                              void* d_out, int out_size)
{
    const int* edges = (const int*)d_in[0];
    int p = (in_sizes[1] <= 2) ? 2 : 1;
    const float* poh   = (const float*)d_in[p+0];
    const float* emb   = (const float*)d_in[p+1];
    const float* W1    = (const float*)d_in[p+2];
    const float* b1    = (const float*)d_in[p+3];
    const float* gamma = (const float*)d_in[p+4];
    const float* beta  = (const float*)d_in[p+5];
    const float* W2    = (const float*)d_in[p+6];
    const float* b2    = (const float*)d_in[p+7];
    float* out = (float*)d_out;

    cudaFuncSetAttribute(k_mlp, cudaFuncAttributeMaxDynamicSharedMemorySize, SMEM_TOTAL);

    k_zero_cnt<<<(NROW + 255)/256, 256>>>();
    k_build  <<<(Bg*Eg + 255)/256, 256>>>(edges);
    k_argmax <<<(Nn + 255)/256, 256>>>(poh);
    k_gather <<<(Nn*16 + 255)/256, 256>>>(emb);
    k_convW1 <<<512, 256>>>(W1);
    k_convW2 <<<512, 256>>>(W2);
    for (int h = 1; h <= 4; h++)
        k_hop<<<(NROW*16 + 255)/256, 256>>>(h);
    k_mlp<<<NROW/64, 256, SMEM_TOTAL>>>(b1, gamma, beta, b2, out);
}

// round 6
// speedup vs baseline: 1.9030x; 1.1223x over previous
#include <cuda_runtime.h>
#include <cuda_bf16.h>
#include <math.h>
#include <stdint.h>

#define Bg 8
#define Nn 20000
#define Eg 320000
#define Cc 128
#define Dd 64
#define CAP 96
#define NROW (Bg*Nn)

// ---------------- device scratch ----------------
__device__ int   g_cnt[NROW];
__device__ int   g_adj[(size_t)NROW*CAP];
__device__ int   g_idx[Nn];
__device__ float g_init[Nn*Dd];
__device__ float g_omega[(size_t)NROW*256];
__device__ __nv_bfloat16 g_w1hi[512*256];
__device__ __nv_bfloat16 g_w1lo[512*256];
__device__ __nv_bfloat16 g_w2hi[256*512];
__device__ __nv_bfloat16 g_w2lo[256*512];

// ---------------- graph kernels (unchanged, proven) ----------------
__global__ void k_zero_cnt(){
    int i = blockIdx.x*blockDim.x + threadIdx.x;
    if (i < NROW) g_cnt[i] = 0;
}
__global__ void k_build(const int* __restrict__ edges){
    int i = blockIdx.x*blockDim.x + threadIdx.x;
    if (i >= Bg*Eg) return;
    int b = i / Eg, e = i % Eg;
    const int* eb = edges + (size_t)b*2*Eg;
    int row = b*Nn + eb[e];
    int c = eb[Eg + e];
    int slot = atomicAdd(&g_cnt[row], 1);
    if (slot < CAP) g_adj[(size_t)row*CAP + slot] = c;
}
__global__ void k_argmax(const float* __restrict__ poh){
    int n = blockIdx.x*blockDim.x + threadIdx.x;
    if (n >= Nn) return;
    float best = poh[n]; int bi = 0;
    #pragma unroll 4
    for (int c = 1; c < Cc; c++){
        float v = poh[(size_t)c*Nn + n];
        if (v > best){ best = v; bi = c; }
    }
    g_idx[n] = bi;
}
__global__ void k_gather(const float* __restrict__ emb){
    int i = blockIdx.x*blockDim.x + threadIdx.x;
    if (i >= Nn*16) return;
    int n = i >> 4, l = i & 15;
    float4 v = *(const float4*)(emb + (size_t)g_idx[n]*Dd + l*4);
    *(float4*)(g_init + (size_t)n*Dd + l*4) = v;
}
__global__ void k_hop(int hop){
    int gid = blockIdx.x*blockDim.x + threadIdx.x;
    int row = gid >> 4, lane = gid & 15;
    if (row >= NROW) return;
    int b = row / Nn;
    const float* src; int rs;
    if (hop == 1){ src = g_init + lane*4; rs = Dd; }
    else         { src = g_omega + (size_t)b*Nn*256 + (hop-2)*Dd + lane*4; rs = 256; }
    int cnt = g_cnt[row]; if (cnt > CAP) cnt = CAP;
    const int* adj = g_adj + (size_t)row*CAP;
    float4 s0 = make_float4(0.f,0.f,0.f,0.f), s1 = make_float4(0.f,0.f,0.f,0.f);
    int j = 0;
    for (; j + 2 <= cnt; j += 2){
        int c0 = adj[j], c1 = adj[j+1];
        float4 v0 = *(const float4*)(src + (size_t)c0*rs);
        float4 v1 = *(const float4*)(src + (size_t)c1*rs);
        s0.x += v0.x; s0.y += v0.y; s0.z += v0.z; s0.w += v0.w;
        s1.x += v1.x; s1.y += v1.y; s1.z += v1.z; s1.w += v1.w;
    }
    if (j < cnt){
        float4 v = *(const float4*)(src + (size_t)adj[j]*rs);
        s0.x += v.x; s0.y += v.y; s0.z += v.z; s0.w += v.w;
    }
    float4 r = make_float4(s0.x+s1.x, s0.y+s1.y, s0.z+s1.z, s0.w+s1.w);
    *(float4*)(g_omega + (size_t)row*256 + (hop-1)*Dd + lane*4) = r;
}

// ---------------- weight split/blocking (unchanged) ----------------
__global__ void k_convW1(const float* __restrict__ W1){
    int i = blockIdx.x*256 + threadIdx.x;
    if (i >= 256*512) return;
    int k = i >> 9, n = i & 511;
    int d = k & 63, h = k >> 6;
    float v = W1[(size_t)(d*4 + h)*512 + n];
    __nv_bfloat16 hb = __float2bfloat16(v);
    float lo = v - __bfloat162float(hb);
    int nc = n >> 8, nn = n & 255, kc = k >> 4, kk = k & 15;
    int off = ((nc*16 + kc)*256 + nn)*16 + kk;
    g_w1hi[off] = hb; g_w1lo[off] = __float2bfloat16(lo);
}
__global__ void k_convW2(const float* __restrict__ W2){
    int i = blockIdx.x*256 + threadIdx.x;
    if (i >= 512*256) return;
    int k = i >> 8, n = i & 255;
    float v = W2[(size_t)k*256 + n];
    __nv_bfloat16 hb = __float2bfloat16(v);
    float lo = v - __bfloat162float(hb);
    int kc = k >> 4, kk = k & 15;
    int off = (kc*256 + n)*16 + kk;
    g_w2hi[off] = hb; g_w2lo[off] = __float2bfloat16(lo);
}

// ---------------- fused MLP (ldmatrix + mma.sync, term-major MMA order) ----------------
#define AST2 264
#define XST2 520
#define BST  24
#define OFF_AH 0
#define OFF_AL 33792
#define OFF_XH 67584
#define OFF_XL 134144
#define OFF_BH 200704
#define OFF_BL 212992
#define OFF_SC 225280
#define SMEM_TOTAL 229376

__device__ __forceinline__ uint32_t smem_u32(const void* p){
    uint32_t a;
    asm("{ .reg .u64 t; cvta.to.shared.u64 t, %1; cvt.u32.u64 %0, t; }" : "=r"(a) : "l"(p));
    return a;
}
__device__ __forceinline__ void ldmx4(unsigned* r, uint32_t addr){
    asm volatile("ldmatrix.sync.aligned.m8n8.x4.shared.b16 {%0,%1,%2,%3}, [%4];"
        : "=r"(r[0]), "=r"(r[1]), "=r"(r[2]), "=r"(r[3]) : "r"(addr));
}
__device__ __forceinline__ void mma_bf16(float* d, const unsigned* a, unsigned b0, unsigned b1){
    asm volatile(
      "mma.sync.aligned.m16n8k16.row.col.f32.bf16.bf16.f32 "
      "{%0,%1,%2,%3},{%4,%5,%6,%7},{%8,%9},{%0,%1,%2,%3};"
      : "+f"(d[0]), "+f"(d[1]), "+f"(d[2]), "+f"(d[3])
      : "r"(a[0]), "r"(a[1]), "r"(a[2]), "r"(a[3]), "r"(b0), "r"(b1));
}
__device__ __forceinline__ void split2(float x, float y, unsigned &hi, unsigned &lo){
    __nv_bfloat162 h = __floats2bfloat162_rn(x, y);
    float lx = x - __bfloat162float(__low2bfloat16(h));
    float ly = y - __bfloat162float(__high2bfloat16(h));
    __nv_bfloat162 l = __floats2bfloat162_rn(lx, ly);
    hi = *reinterpret_cast<unsigned*>(&h);
    lo = *reinterpret_cast<unsigned*>(&l);
}
__device__ __forceinline__ float2 rec2(unsigned h, unsigned l){
    __nv_bfloat162 hb = *reinterpret_cast<__nv_bfloat162*>(&h);
    __nv_bfloat162 lb = *reinterpret_cast<__nv_bfloat162*>(&l);
    return make_float2(__low2float(hb) + __low2float(lb),
                       __high2float(hb) + __high2float(lb));
}

template<int NK, int ASTRIDE>
__device__ __forceinline__ void gemm_pass(
    uint32_t aHi, uint32_t aLo,
    const __nv_bfloat16* __restrict__ gBh, const __nv_bfloat16* __restrict__ gBl,
    char* sm, uint32_t smb, int tid, int w, float acc[4][4][4])
{
    int lane = tid & 31;
    int arow = lane & 15, akh = (lane >> 4) * 8;
    int brow = (lane & 7) + ((lane >> 4) & 1) * 8;
    int bko  = ((lane >> 3) & 1) * 8;
    int i0 = tid, i1 = tid + 256;
    uint32_t s0 = (uint32_t)(((i0 >> 1)*BST + (i0 & 1)*8)*2);
    uint32_t s1 = (uint32_t)(((i1 >> 1)*BST + (i1 & 1)*8)*2);
    {
        const uint4* ph = (const uint4*)gBh;
        const uint4* pl = (const uint4*)gBl;
        uint4 c0 = ph[i0], c1 = ph[i1], c2 = pl[i0], c3 = pl[i1];
        *(uint4*)(sm + OFF_BH + s0) = c0; *(uint4*)(sm + OFF_BH + s1) = c1;
        *(uint4*)(sm + OFF_BL + s0) = c2; *(uint4*)(sm + OFF_BL + s1) = c3;
    }
    __syncthreads();
    for (int kc = 0; kc < NK; kc++){
        uint4 p0, p1, p2, p3;
        bool pre = (kc + 1 < NK);
        if (pre){
            const uint4* ph = (const uint4*)(gBh + (size_t)(kc+1)*4096);
            const uint4* pl = (const uint4*)(gBl + (size_t)(kc+1)*4096);
            p0 = ph[i0]; p1 = ph[i1]; p2 = pl[i0]; p3 = pl[i1];
        }
        unsigned ah[4][4], al[4][4];
        uint32_t abase = (uint32_t)((arow*ASTRIDE + kc*16 + akh)*2);
        #pragma unroll
        for (int i = 0; i < 4; i++){
            ldmx4(ah[i], aHi + abase + (uint32_t)(i*16*ASTRIDE*2));
            ldmx4(al[i], aLo + abase + (uint32_t)(i*16*ASTRIDE*2));
        }
        unsigned bh[2][4], bl[2][4];
        #pragma unroll
        for (int jj = 0; jj < 2; jj++){
            uint32_t boff = (uint32_t)((((w*32 + jj*16) + brow)*BST + bko)*2);
            ldmx4(bh[jj], smb + OFF_BH + boff);
            ldmx4(bl[jj], smb + OFF_BL + boff);
        }
        // term-major issue order: same-acc MMAs are 16 apart -> no RAW stalls
        #pragma unroll
        for (int t = 0; t < 3; t++){
            #pragma unroll
            for (int j = 0; j < 4; j++){
                unsigned b0 = (t == 1) ? bl[j>>1][(j&1)*2]   : bh[j>>1][(j&1)*2];
                unsigned b1 = (t == 1) ? bl[j>>1][(j&1)*2+1] : bh[j>>1][(j&1)*2+1];
                #pragma unroll
                for (int i = 0; i < 4; i++){
                    mma_bf16(acc[i][j], (t == 2) ? al[i] : ah[i], b0, b1);
                }
            }
        }
        __syncthreads();
        if (pre){
            *(uint4*)(sm + OFF_BH + s0) = p0; *(uint4*)(sm + OFF_BH + s1) = p1;
            *(uint4*)(sm + OFF_BL + s0) = p2; *(uint4*)(sm + OFF_BL + s1) = p3;
            __syncthreads();
        }
    }
}

__global__ void __launch_bounds__(256,1) k_mlp(
    const float* __restrict__ b1v, const float* __restrict__ gamma,
    const float* __restrict__ beta, const float* __restrict__ b2v,
    float* __restrict__ out)
{
    extern __shared__ char sm[];
    uint32_t smb = smem_u32(sm);
    float* SC = (float*)(sm + OFF_SC);

    int tid = threadIdx.x;
    int lane = tid & 31, w = tid >> 5;
    int gid = lane >> 2, tig = lane & 3;
    int rowBase = blockIdx.x * 64;

    // ---- load A tile [64][256], split fp32 -> bf16 hi/lo into smem ----
    for (int i = tid; i < 4096; i += 256){
        int r = i >> 6, c = (i & 63)*4;
        float4 v = *(const float4*)(g_omega + (size_t)(rowBase + r)*256 + c);
        unsigned h0, l0, h1, l1;
        split2(v.x, v.y, h0, l0);
        split2(v.z, v.w, h1, l1);
        *(uint2*)(sm + OFF_AH + (size_t)(r*AST2 + c)*2) = make_uint2(h0, h1);
        *(uint2*)(sm + OFF_AL + (size_t)(r*AST2 + c)*2) = make_uint2(l0, l1);
    }
    __syncthreads();

    float acc[4][4][4];

    // ---- GEMM1: X = A @ W1p, two 256-col chunks, K=256 ----
    for (int nc = 0; nc < 2; nc++){
        #pragma unroll
        for (int i = 0; i < 4; i++)
            #pragma unroll
            for (int j = 0; j < 4; j++)
                #pragma unroll
                for (int q = 0; q < 4; q++) acc[i][j][q] = 0.f;

        gemm_pass<16, AST2>(smb + OFF_AH, smb + OFF_AL,
                            g_w1hi + (size_t)nc*16*4096, g_w1lo + (size_t)nc*16*4096,
                            sm, smb, tid, w, acc);

        #pragma unroll
        for (int j = 0; j < 4; j++){
            int col = nc*256 + w*32 + j*8 + tig*2;
            float ba = __ldg(b1v + col), bb = __ldg(b1v + col + 1);
            #pragma unroll
            for (int i = 0; i < 4; i++){
                int r = i*16 + gid;
                unsigned h, l;
                split2(acc[i][j][0] + ba, acc[i][j][1] + bb, h, l);
                *(unsigned*)(sm + OFF_XH + (size_t)(r*XST2 + col)*2) = h;
                *(unsigned*)(sm + OFF_XL + (size_t)(r*XST2 + col)*2) = l;
                split2(acc[i][j][2] + ba, acc[i][j][3] + bb, h, l);
                *(unsigned*)(sm + OFF_XH + (size_t)((r+8)*XST2 + col)*2) = h;
                *(unsigned*)(sm + OFF_XL + (size_t)((r+8)*XST2 + col)*2) = l;
            }
        }
        __syncthreads();
    }

    // ---- LayerNorm + GELU on X (hi/lo reconstruct, in place) ----
    {
        int r = tid & 63, q = tid >> 6;
        char* xh = sm + OFF_XH + (size_t)(r*XST2 + q*128)*2;
        char* xl = sm + OFF_XL + (size_t)(r*XST2 + q*128)*2;
        float s = 0.f, s2 = 0.f;
        #pragma unroll
        for (int i = 0; i < 16; i++){
            uint4 hv = *(uint4*)(xh + i*16);
            uint4 lv = *(uint4*)(xl + i*16);
            float2 e;
            e = rec2(hv.x, lv.x); s += e.x + e.y; s2 += e.x*e.x + e.y*e.y;
            e = rec2(hv.y, lv.y); s += e.x + e.y; s2 += e.x*e.x + e.y*e.y;
            e = rec2(hv.z, lv.z); s += e.x + e.y; s2 += e.x*e.x + e.y*e.y;
            e = rec2(hv.w, lv.w); s += e.x + e.y; s2 += e.x*e.x + e.y*e.y;
        }
        SC[q*64 + r] = s; SC[256 + q*64 + r] = s2;
        __syncthreads();
        if (tid < 64){
            float S  = SC[tid] + SC[64+tid] + SC[128+tid] + SC[192+tid];
            float S2 = SC[256+tid] + SC[320+tid] + SC[384+tid] + SC[448+tid];
            float mu  = S * (1.f/512.f);
            float var = S2 * (1.f/512.f) - mu*mu;
            SC[512 + tid] = mu;
            SC[576 + tid] = rsqrtf(var + 1e-5f);
        }
        __syncthreads();
        float mu = SC[512 + r], rsg = SC[576 + r];
        #pragma unroll
        for (int i = 0; i < 16; i++){
            uint4 hv = *(uint4*)(xh + i*16);
            uint4 lv = *(uint4*)(xl + i*16);
            unsigned hw[4], lw[4];
            unsigned* hvp = (unsigned*)&hv;
            unsigned* lvp = (unsigned*)&lv;
            #pragma unroll
            for (int t = 0; t < 4; t++){
                float2 e = rec2(hvp[t], lvp[t]);
                int c = q*128 + i*8 + t*2;
                float g0 = __ldg(gamma + c), g1 = __ldg(gamma + c + 1);
                float be0 = __ldg(beta + c), be1 = __ldg(beta + c + 1);
                e.x = (e.x - mu)*rsg*g0 + be0;
                e.y = (e.y - mu)*rsg*g1 + be1;
                e.x = 0.5f*e.x*(1.f + erff(e.x*0.70710678118654752f));
                e.y = 0.5f*e.y*(1.f + erff(e.y*0.70710678118654752f));
                split2(e.x, e.y, hw[t], lw[t]);
            }
            *(uint4*)(xh + i*16) = make_uint4(hw[0], hw[1], hw[2], hw[3]);
            *(uint4*)(xl + i*16) = make_uint4(lw[0], lw[1], lw[2], lw[3]);
        }
        __syncthreads();
    }

    // ---- GEMM2: OUT = X @ W2, one 256-col chunk, K=512 ----
    #pragma unroll
    for (int i = 0; i < 4; i++)
        #pragma unroll
        for (int j = 0; j < 4; j++)
            #pragma unroll
            for (int q = 0; q < 4; q++) acc[i][j][q] = 0.f;

    gemm_pass<32, XST2>(smb + OFF_XH, smb + OFF_XL, g_w2hi, g_w2lo,
                        sm, smb, tid, w, acc);

    #pragma unroll
    for (int j = 0; j < 4; j++){
        int col = w*32 + j*8 + tig*2;
        float ba = __ldg(b2v + col), bb = __ldg(b2v + col + 1);
        #pragma unroll
        for (int i = 0; i < 4; i++){
            int r = i*16 + gid;
            *(float2*)(out + (size_t)(rowBase + r)*256 + col)     = make_float2(acc[i][j][0] + ba, acc[i][j][1] + bb);
            *(float2*)(out + (size_t)(rowBase + r + 8)*256 + col) = make_float2(acc[i][j][2] + ba, acc[i][j][3] + bb);
        }
    }
}

// ---------------- launch ----------------
extern "C" void kernel_launch(void* const* d_in, const int* in_sizes, int n_in,
                              void* d_out, int out_size)
{
    const int* edges = (const int*)d_in[0];
    int p = (in_sizes[1] <= 2) ? 2 : 1;
    const float* poh   = (const float*)d_in[p+0];
    const float* emb   = (const float*)d_in[p+1];
    const float* W1    = (const float*)d_in[p+2];
    const float* b1    = (const float*)d_in[p+3];
    const float* gamma = (const float*)d_in[p+4];
    const float* beta  = (const float*)d_in[p+5];
    const float* W2    = (const float*)d_in[p+6];
    const float* b2    = (const float*)d_in[p+7];
    float* out = (float*)d_out;

    cudaFuncSetAttribute(k_mlp, cudaFuncAttributeMaxDynamicSharedMemorySize, SMEM_TOTAL);

    k_zero_cnt<<<(NROW + 255)/256, 256>>>();
    k_build  <<<(Bg*Eg + 255)/256, 256>>>(edges);
    k_argmax <<<(Nn + 255)/256, 256>>>(poh);
    k_gather <<<(Nn*16 + 255)/256, 256>>>(emb);
    k_convW1 <<<512, 256>>>(W1);
    k_convW2 <<<512, 256>>>(W2);
    for (int h = 1; h <= 4; h++)
        k_hop<<<(NROW*16 + 255)/256, 256>>>(h);
    k_mlp<<<NROW/64, 256, SMEM_TOTAL>>>(b1, gamma, beta, b2, out);
}